// round 1
// baseline (speedup 1.0000x reference)
#include <cuda_runtime.h>

#define MAX_NODES 50000
#define MAX_EDGES 800000
#define D 128
#define D4 32          // D / 4 (float4 per row)
#define ROWS 32        // rows per block in output kernel

// Scratch (module-static device memory; allocation happens at module load,
// not inside kernel_launch).
__device__ __align__(16) float g_h[MAX_NODES * D];     // gathered node features
__device__ __align__(16) float g_agg[MAX_NODES * D];   // pre-W aggregated messages
__device__ float g_deg[MAX_NODES];                     // in-degree (float)

// ---------------------------------------------------------------------------
// K1: gather h = prev[node_id], zero agg and deg
// ---------------------------------------------------------------------------
__global__ void k_gather_zero(const float* __restrict__ prev,
                              const int* __restrict__ node_id,
                              int n_nodes)
{
    int i = blockIdx.x * blockDim.x + threadIdx.x;   // over n_nodes * D4 float4s
    int total = n_nodes * D4;
    if (i >= total) return;
    int row = i >> 5;          // / D4
    int col = i & 31;
    int ent = __ldg(node_id + row);
    float4 v = __ldg(reinterpret_cast<const float4*>(prev) + (long long)ent * D4 + col);
    reinterpret_cast<float4*>(g_h)[i] = v;
    reinterpret_cast<float4*>(g_agg)[i] = make_float4(0.f, 0.f, 0.f, 0.f);
    if (col == 0) g_deg[row] = 0.f;
}

// ---------------------------------------------------------------------------
// K2: per-edge scatter. One warp per edge: read h[src] row (+ rel[etype]),
// vector-reduce into agg[dst]. deg[dst] += 1 from lane 0.
// ---------------------------------------------------------------------------
__global__ void k_edge_scatter(const float* __restrict__ rel,
                               const int* __restrict__ src,
                               const int* __restrict__ dst,
                               const int* __restrict__ etype,
                               int n_edges)
{
    int lane  = threadIdx.x & 31;
    int warp  = (blockIdx.x * blockDim.x + threadIdx.x) >> 5;
    int nwarp = (gridDim.x * blockDim.x) >> 5;

    const float4* h4 = reinterpret_cast<const float4*>(g_h);
    const float4* r4 = reinterpret_cast<const float4*>(rel);
    float4* agg4 = reinterpret_cast<float4*>(g_agg);

    for (int e = warp; e < n_edges; e += nwarp) {
        int s = __ldg(src + e);
        int d = __ldg(dst + e);
        int t = __ldg(etype + e);
        float4 a = h4[s * D4 + lane];
        float4 r = __ldg(r4 + t * D4 + lane);
        float4* p = agg4 + d * D4 + lane;
        asm volatile("red.global.add.v4.f32 [%0], {%1,%2,%3,%4};"
                     :: "l"(p),
                        "f"(a.x + r.x), "f"(a.y + r.y),
                        "f"(a.z + r.z), "f"(a.w + r.w)
                     : "memory");
        if (lane == 0) {
            asm volatile("red.global.add.f32 [%0], %1;"
                         :: "l"(g_deg + d), "f"(1.0f) : "memory");
        }
    }
}

// ---------------------------------------------------------------------------
// K3: out = relu( (agg * norm) @ Wn + h @ (deg>0 ? Wl : We) )
// Wn, Wl staged in SMEM; 32 rows per block; 4x4 register tile per thread.
// deg==0 rows (statistically ~none) recompute the self-loop term with We
// read through L2.
// ---------------------------------------------------------------------------
__global__ void __launch_bounds__(256, 1)
k_output(const float* __restrict__ Wl, const float* __restrict__ We,
         const float* __restrict__ Wn, float* __restrict__ out, int n_nodes)
{
    extern __shared__ float sm[];
    float* Wn_s  = sm;                    // D*D
    float* Wl_s  = Wn_s + D * D;          // D*D
    float* z_s   = Wl_s + D * D;          // ROWS*D  (agg * norm)
    float* h_s   = z_s + ROWS * D;        // ROWS*D
    float* deg_s = h_s + ROWS * D;        // ROWS

    int tid = threadIdx.x;

    // stage weights
    for (int i = tid; i < (D * D) / 4; i += 256) {
        reinterpret_cast<float4*>(Wn_s)[i] = __ldg(reinterpret_cast<const float4*>(Wn) + i);
        reinterpret_cast<float4*>(Wl_s)[i] = __ldg(reinterpret_cast<const float4*>(Wl) + i);
    }

    int row0 = blockIdx.x * ROWS;

    // stage z = agg * norm and h rows
    for (int i = tid; i < ROWS * D4; i += 256) {
        int r = i >> 5;
        int c = i & 31;
        int grow = row0 + r;
        float4 hv = make_float4(0.f, 0.f, 0.f, 0.f);
        float4 zv = hv;
        float dg = 0.f;
        if (grow < n_nodes) {
            hv = reinterpret_cast<const float4*>(g_h)[grow * D4 + c];
            dg = g_deg[grow];
            float nrm = dg > 0.f ? 1.0f / dg : 0.f;
            float4 av = reinterpret_cast<const float4*>(g_agg)[grow * D4 + c];
            zv = make_float4(av.x * nrm, av.y * nrm, av.z * nrm, av.w * nrm);
        }
        reinterpret_cast<float4*>(h_s)[i] = hv;
        reinterpret_cast<float4*>(z_s)[i] = zv;
        if (c == 0) deg_s[r] = dg;
    }
    __syncthreads();

    int cg = (tid & 31) * 4;    // base output column (0..124)
    int rg = (tid >> 5) * 4;    // base row within tile (0..28)

    float accN[4][4];
    float accL[4][4];
    #pragma unroll
    for (int r = 0; r < 4; r++)
        #pragma unroll
        for (int c = 0; c < 4; c++) { accN[r][c] = 0.f; accL[r][c] = 0.f; }

    #pragma unroll 2
    for (int k = 0; k < D; k++) {
        float4 wn = reinterpret_cast<const float4*>(Wn_s)[(k * D + cg) >> 2];
        float4 wl = reinterpret_cast<const float4*>(Wl_s)[(k * D + cg) >> 2];
        #pragma unroll
        for (int r = 0; r < 4; r++) {
            float zk = z_s[(rg + r) * D + k];
            float hk = h_s[(rg + r) * D + k];
            accN[r][0] += zk * wn.x; accN[r][1] += zk * wn.y;
            accN[r][2] += zk * wn.z; accN[r][3] += zk * wn.w;
            accL[r][0] += hk * wl.x; accL[r][1] += hk * wl.y;
            accL[r][2] += hk * wl.z; accL[r][3] += hk * wl.w;
        }
    }

    #pragma unroll
    for (int r = 0; r < 4; r++) {
        int grow = row0 + rg + r;
        if (grow >= n_nodes) continue;
        float l0 = accL[r][0], l1 = accL[r][1], l2 = accL[r][2], l3 = accL[r][3];
        if (deg_s[rg + r] <= 0.f) {
            // rare: no in-edges -> self-loop uses evolve_loop_weight
            l0 = l1 = l2 = l3 = 0.f;
            for (int k = 0; k < D; k++) {
                float hk = h_s[(rg + r) * D + k];
                float4 we = __ldg(reinterpret_cast<const float4*>(We) + ((k * D + cg) >> 2));
                l0 += hk * we.x; l1 += hk * we.y; l2 += hk * we.z; l3 += hk * we.w;
            }
        }
        float v0 = accN[r][0] + l0;
        float v1 = accN[r][1] + l1;
        float v2 = accN[r][2] + l2;
        float v3 = accN[r][3] + l3;
        float4 o = make_float4(v0 > 0.f ? v0 : 0.f,
                               v1 > 0.f ? v1 : 0.f,
                               v2 > 0.f ? v2 : 0.f,
                               v3 > 0.f ? v3 : 0.f);
        *reinterpret_cast<float4*>(out + grow * D + cg) = o;
    }
}

// ---------------------------------------------------------------------------
extern "C" void kernel_launch(void* const* d_in, const int* in_sizes, int n_in,
                              void* d_out, int out_size)
{
    const float* prev    = (const float*)d_in[0];
    const float* rel     = (const float*)d_in[1];
    const float* Wl      = (const float*)d_in[2];
    const float* We      = (const float*)d_in[3];
    const float* Wn      = (const float*)d_in[4];
    const int*   node_id = (const int*)d_in[5];
    const int*   src     = (const int*)d_in[6];
    const int*   dst     = (const int*)d_in[7];
    const int*   ety     = (const int*)d_in[8];
    float* out = (float*)d_out;

    int n_nodes = in_sizes[5];
    int n_edges = in_sizes[6];

    // K1: gather + zero
    {
        int total = n_nodes * D4;
        int blocks = (total + 255) / 256;
        k_gather_zero<<<blocks, 256>>>(prev, node_id, n_nodes);
    }

    // K2: edge scatter (persistent-ish grid: 8 blocks/SM x 148 SMs)
    k_edge_scatter<<<1184, 256>>>(rel, src, dst, ety, n_edges);

    // K3: output GEMM + epilogue
    {
        size_t smem = (size_t)(D * D * 2 + ROWS * D * 2 + ROWS) * sizeof(float);
        cudaFuncSetAttribute(k_output, cudaFuncAttributeMaxDynamicSharedMemorySize,
                             (int)smem);
        int blocks = (n_nodes + ROWS - 1) / ROWS;
        k_output<<<blocks, 256, smem>>>(Wl, We, Wn, out, n_nodes);
    }
}

// round 2
// speedup vs baseline: 1.4497x; 1.4497x over previous
#include <cuda_runtime.h>

#define D 128
#define D4 32
#define MAXN 50048
#define MAXE 800000
#define ROWS3 64
#define THR3 512

typedef unsigned long long ull;

// ---- scratch (module-static device memory) ----
__device__ __align__(16) float g_h[MAXN * D];   // gathered node features
__device__ __align__(16) float g_z[MAXN * D];   // normalized aggregate (agg/deg)
__device__ int   g_cnt[MAXN];                   // in-degree (int)
__device__ int   g_off[MAXN];                   // CSR offsets
__device__ int   g_cur[MAXN];                   // scatter cursors
__device__ float g_deg[MAXN];                   // in-degree (float)
__device__ int   g_bsum[128];                   // scan block sums
__device__ int   g_es[MAXE];                    // edge src, sorted by dst
__device__ int   g_et[MAXE];                    // edge etype, sorted by dst

#define FMA2(acc, a, b) \
    asm("fma.rn.f32x2 %0, %1, %2, %3;" : "=l"(acc) : "l"(a), "l"(b), "l"(acc))

// ---------------------------------------------------------------------------
// K1: h = prev[node_id]; zero degree counters
// ---------------------------------------------------------------------------
__global__ void k_gather(const float* __restrict__ prev,
                         const int* __restrict__ node_id, int n)
{
    int i = blockIdx.x * 256 + threadIdx.x;       // over n * D4 float4s
    if (i >= n * D4) return;
    int row = i >> 5, col = i & 31;
    int ent = __ldg(node_id + row);
    float4 v = __ldg(reinterpret_cast<const float4*>(prev) + (size_t)ent * D4 + col);
    reinterpret_cast<float4*>(g_h)[i] = v;
    if (col == 0) g_cnt[row] = 0;
}

// ---------------------------------------------------------------------------
// K2a: histogram of dst
// ---------------------------------------------------------------------------
__global__ void k_hist(const int* __restrict__ dst, int ne)
{
    int e = blockIdx.x * 256 + threadIdx.x;
    if (e >= ne) return;
    atomicAdd(&g_cnt[__ldg(dst + e)], 1);
}

// ---------------------------------------------------------------------------
// K2b/c/d: exclusive scan of g_cnt -> g_off (chunked Hillis-Steele)
// ---------------------------------------------------------------------------
__global__ void k_scan1(int n)
{
    __shared__ int sm[1024];
    int t = threadIdx.x;
    int i = blockIdx.x * 1024 + t;
    int v = (i < n) ? g_cnt[i] : 0;
    sm[t] = v;
    __syncthreads();
    #pragma unroll
    for (int off = 1; off < 1024; off <<= 1) {
        int x = (t >= off) ? sm[t - off] : 0;
        __syncthreads();
        sm[t] += x;
        __syncthreads();
    }
    if (i < n) g_off[i] = sm[t] - v;              // exclusive within chunk
    if (t == 1023) g_bsum[blockIdx.x] = sm[t];    // chunk total
}

__global__ void k_scan2(int nchunks)
{
    __shared__ int sm[128];
    int t = threadIdx.x;
    if (t < nchunks) sm[t] = g_bsum[t];
    __syncthreads();
    if (t == 0) {
        int run = 0;
        for (int b = 0; b < nchunks; b++) { int x = sm[b]; sm[b] = run; run += x; }
    }
    __syncthreads();
    if (t < nchunks) g_bsum[t] = sm[t];
}

__global__ void k_scan3(int n)
{
    int i = blockIdx.x * 256 + threadIdx.x;
    if (i >= n) return;
    int o = g_off[i] + g_bsum[i >> 10];
    g_off[i] = o;
    g_cur[i] = o;
    g_deg[i] = (float)g_cnt[i];
}

// ---------------------------------------------------------------------------
// K2e: permute edge (src, etype) into dst-sorted order
// ---------------------------------------------------------------------------
__global__ void k_perm(const int* __restrict__ src, const int* __restrict__ dst,
                       const int* __restrict__ ety, int ne)
{
    int e = blockIdx.x * 256 + threadIdx.x;
    if (e >= ne) return;
    int d = __ldg(dst + e);
    int pos = atomicAdd(&g_cur[d], 1);
    g_es[pos] = __ldg(src + e);
    g_et[pos] = __ldg(ety + e);
}

// ---------------------------------------------------------------------------
// K2f: one warp per node: z[n] = (1/deg) * sum_e (h[src_e] + rel[etype_e])
// ---------------------------------------------------------------------------
__global__ void k_agg(const float* __restrict__ rel, int n)
{
    int lane = threadIdx.x & 31;
    int node = (blockIdx.x * blockDim.x + threadIdx.x) >> 5;
    if (node >= n) return;
    int beg = g_off[node];
    int cnt = g_cnt[node];

    const float4* h4 = reinterpret_cast<const float4*>(g_h);
    const float4* r4 = reinterpret_cast<const float4*>(rel);

    float4 acc = make_float4(0.f, 0.f, 0.f, 0.f);
    int j = 0;
    for (; j + 1 < cnt; j += 2) {
        int s0 = __ldg(g_es + beg + j);
        int t0 = __ldg(g_et + beg + j);
        int s1 = __ldg(g_es + beg + j + 1);
        int t1 = __ldg(g_et + beg + j + 1);
        float4 a0 = h4[s0 * D4 + lane];
        float4 b0 = __ldg(r4 + t0 * D4 + lane);
        float4 a1 = h4[s1 * D4 + lane];
        float4 b1 = __ldg(r4 + t1 * D4 + lane);
        acc.x += (a0.x + b0.x) + (a1.x + b1.x);
        acc.y += (a0.y + b0.y) + (a1.y + b1.y);
        acc.z += (a0.z + b0.z) + (a1.z + b1.z);
        acc.w += (a0.w + b0.w) + (a1.w + b1.w);
    }
    if (j < cnt) {
        int s0 = __ldg(g_es + beg + j);
        int t0 = __ldg(g_et + beg + j);
        float4 a0 = h4[s0 * D4 + lane];
        float4 b0 = __ldg(r4 + t0 * D4 + lane);
        acc.x += a0.x + b0.x;
        acc.y += a0.y + b0.y;
        acc.z += a0.z + b0.z;
        acc.w += a0.w + b0.w;
    }
    float inv = (cnt > 0) ? 1.0f / (float)cnt : 0.f;
    acc.x *= inv; acc.y *= inv; acc.z *= inv; acc.w *= inv;
    reinterpret_cast<float4*>(g_z)[node * D4 + lane] = acc;
}

// ---------------------------------------------------------------------------
// K3: out = relu( z @ Wn + h @ (deg>0 ? Wl : We) )
// Persistent: weights staged once per SM in k-pair layout; f32x2 FMA mainloop.
// Layout: WP[kp*256 + c*2 + j] = W[(2*kp+j)*D + c]
// ---------------------------------------------------------------------------
__global__ void __launch_bounds__(THR3, 1)
k_out(const float* __restrict__ Wl, const float* __restrict__ We,
      const float* __restrict__ Wn, float* __restrict__ out, int n)
{
    extern __shared__ float sm[];
    float* WnP  = sm;                     // 64*256 floats
    float* WlP  = WnP + 64 * 256;         // 64*256 floats
    float* zs   = WlP + 64 * 256;         // ROWS3*D
    float* hs   = zs + ROWS3 * D;         // ROWS3*D
    float* degs = hs + ROWS3 * D;         // ROWS3

    int tid = threadIdx.x;

    // stage weights once (k-pair layout)
    for (int i = tid; i < D * D; i += THR3) {
        int k = i >> 7, c = i & 127;      // coalesced over c
        float wn = __ldg(Wn + i);
        float wl = __ldg(Wl + i);
        int idx = (k >> 1) * 256 + c * 2 + (k & 1);
        WnP[idx] = wn;
        WlP[idx] = wl;
    }

    int cg = (tid & 63) * 2;              // 2 output columns per thread
    int rg = (tid >> 6) * 8;              // 8 rows per thread
    int ntile = (n + ROWS3 - 1) / ROWS3;

    for (int tile = blockIdx.x; tile < ntile; tile += gridDim.x) {
        int row0 = tile * ROWS3;
        __syncthreads();
        // stage z, h, deg for this tile
        for (int i = tid; i < ROWS3 * D4; i += THR3) {
            int r = i >> 5, c = i & 31;
            int gr = row0 + r;
            float4 zv = make_float4(0.f, 0.f, 0.f, 0.f);
            float4 hv = zv;
            float dg = 1.f;
            if (gr < n) {
                zv = reinterpret_cast<const float4*>(g_z)[gr * D4 + c];
                hv = reinterpret_cast<const float4*>(g_h)[gr * D4 + c];
                dg = g_deg[gr];
            }
            reinterpret_cast<float4*>(zs)[i] = zv;
            reinterpret_cast<float4*>(hs)[i] = hv;
            if (c == 0) degs[r] = dg;
        }
        __syncthreads();

        ull accN[8][2] = {};
        ull accL[8][2] = {};

        #pragma unroll 4
        for (int k4 = 0; k4 < D; k4 += 4) {       // 4 k-values = 2 k-pairs
            int kp = k4 >> 1;
            const float* wq = WnP + kp * 256 + cg * 2;
            const float* wr = WlP + kp * 256 + cg * 2;
            longlong2 wnA = *reinterpret_cast<const longlong2*>(wq);
            longlong2 wnB = *reinterpret_cast<const longlong2*>(wq + 256);
            longlong2 wlA = *reinterpret_cast<const longlong2*>(wr);
            longlong2 wlB = *reinterpret_cast<const longlong2*>(wr + 256);
            #pragma unroll
            for (int r = 0; r < 8; r++) {
                longlong2 zz = *reinterpret_cast<const longlong2*>(zs + (rg + r) * D + k4);
                longlong2 hh = *reinterpret_cast<const longlong2*>(hs + (rg + r) * D + k4);
                ull zx = (ull)zz.x, zy = (ull)zz.y;
                ull hx = (ull)hh.x, hy = (ull)hh.y;
                FMA2(accN[r][0], zx, (ull)wnA.x);
                FMA2(accN[r][1], zx, (ull)wnA.y);
                FMA2(accN[r][0], zy, (ull)wnB.x);
                FMA2(accN[r][1], zy, (ull)wnB.y);
                FMA2(accL[r][0], hx, (ull)wlA.x);
                FMA2(accL[r][1], hx, (ull)wlA.y);
                FMA2(accL[r][0], hy, (ull)wlB.x);
                FMA2(accL[r][1], hy, (ull)wlB.y);
            }
        }

        #pragma unroll
        for (int r = 0; r < 8; r++) {
            int gr = row0 + rg + r;
            if (gr >= n) continue;
            float n0 = __uint_as_float((unsigned)accN[r][0]) +
                       __uint_as_float((unsigned)(accN[r][0] >> 32));
            float n1 = __uint_as_float((unsigned)accN[r][1]) +
                       __uint_as_float((unsigned)(accN[r][1] >> 32));
            float l0 = __uint_as_float((unsigned)accL[r][0]) +
                       __uint_as_float((unsigned)(accL[r][0] >> 32));
            float l1 = __uint_as_float((unsigned)accL[r][1]) +
                       __uint_as_float((unsigned)(accL[r][1] >> 32));
            if (degs[rg + r] <= 0.f) {
                // rare: no in-edges -> self-loop uses evolve_loop_weight
                l0 = 0.f; l1 = 0.f;
                for (int k = 0; k < D; k++) {
                    float hk = hs[(rg + r) * D + k];
                    l0 += hk * __ldg(We + k * D + cg);
                    l1 += hk * __ldg(We + k * D + cg + 1);
                }
            }
            float v0 = n0 + l0;
            float v1 = n1 + l1;
            float2 o = make_float2(v0 > 0.f ? v0 : 0.f, v1 > 0.f ? v1 : 0.f);
            *reinterpret_cast<float2*>(out + (size_t)gr * D + cg) = o;
        }
    }
}

// ---------------------------------------------------------------------------
extern "C" void kernel_launch(void* const* d_in, const int* in_sizes, int n_in,
                              void* d_out, int out_size)
{
    const float* prev    = (const float*)d_in[0];
    const float* rel     = (const float*)d_in[1];
    const float* Wl      = (const float*)d_in[2];
    const float* We      = (const float*)d_in[3];
    const float* Wn      = (const float*)d_in[4];
    const int*   node_id = (const int*)d_in[5];
    const int*   src     = (const int*)d_in[6];
    const int*   dst     = (const int*)d_in[7];
    const int*   ety     = (const int*)d_in[8];
    float* out = (float*)d_out;

    int n_nodes = in_sizes[5];
    int n_edges = in_sizes[6];
    int nchunks = (n_nodes + 1023) / 1024;

    // gather + zero counts
    k_gather<<<(n_nodes * D4 + 255) / 256, 256>>>(prev, node_id, n_nodes);

    // histogram of dst
    k_hist<<<(n_edges + 255) / 256, 256>>>(dst, n_edges);

    // exclusive scan -> CSR offsets, cursors, float deg
    k_scan1<<<nchunks, 1024>>>(n_nodes);
    k_scan2<<<1, 128>>>(nchunks);
    k_scan3<<<(n_nodes + 255) / 256, 256>>>(n_nodes);

    // counting-sort edges by dst
    k_perm<<<(n_edges + 255) / 256, 256>>>(src, dst, ety, n_edges);

    // per-node aggregation (normalized)
    k_agg<<<(n_nodes * 32 + 255) / 256, 256>>>(rel, n_nodes);

    // fused output GEMM (persistent, f32x2)
    {
        size_t smem = (size_t)(2 * 64 * 256 + 2 * ROWS3 * D + ROWS3) * sizeof(float);
        cudaFuncSetAttribute(k_out, cudaFuncAttributeMaxDynamicSharedMemorySize,
                             (int)smem);
        k_out<<<148, THR3, smem>>>(Wl, We, Wn, out, n_nodes);
    }
}